// round 9
// baseline (speedup 1.0000x reference)
#include <cuda_runtime.h>
#include <cstdint>

#define BB 4
#define NN 4096
#define KK 16
#define DP 64
#define DM 128
#define EPSN 1e-8f
#define FINF 3.402823466e38f

// ---------------- scratch (device globals; no allocation allowed) ----------
__device__ float g_q [BB*NN*DM];    // 8 MB   x @ wq
__device__ float g_k [BB*NN*DM];    // 8 MB   x @ wk
__device__ float g_v [BB*NN*DM];    // 8 MB   x @ wv
__device__ float g_qs[BB*NN*DM];    // 8 MB   q @ sim_w[1:]
__device__ float g_ks[BB*NN*DM];    // 8 MB   k @ sim_w[1:]
__device__ float g_qn[BB*NN];       // ||q|| clamped
__device__ float g_kn[BB*NN];       // ||k|| clamped
__device__ int   g_knn[BB*NN*KK];   // 1 MB

// ---------------- packed fp32x2 FMA (Blackwell FFMA2) ----------------------
__device__ __forceinline__ float2 ffma2(float2 a, float2 b, float2 c){
  float2 d;
  asm("fma.rn.f32x2 %0, %1, %2, %3;"
      : "=l"(reinterpret_cast<unsigned long long&>(d))
      : "l"(reinterpret_cast<unsigned long long&>(a)),
        "l"(reinterpret_cast<unsigned long long&>(b)),
        "l"(reinterpret_cast<unsigned long long&>(c)));
  return d;
}

// =================== qkv-style GEMM (256 thr, 128 rows) =====================
// input col-major stride 130; thread (cg=tid&31, rg=tid>>5) = cols cg+32q,
// rows 16rg..16rg+15 (8 float2 pairs).
template<int NCOLS>
__device__ __forceinline__ void gemm4(const float* __restrict__ S, int stride,
                                      const float* __restrict__ W,
                                      int cg, int rg, float2 acc[8][4])
{
  const float* src = S + 16*rg;
  float w[4];
#pragma unroll
  for (int q=0;q<4;++q) w[q] = W[cg + 32*q];
#pragma unroll 2
  for (int c=0;c<NCOLS;++c){
    float wn[4];
    if (c+1 < NCOLS){
#pragma unroll
      for (int q=0;q<4;++q) wn[q] = W[(c+1)*DM + cg + 32*q];
    }
    float2 r[8];
#pragma unroll
    for (int j=0;j<8;++j)
      r[j] = *reinterpret_cast<const float2*>(src + c*stride + 2*j);
#pragma unroll
    for (int j=0;j<8;++j){
#pragma unroll
      for (int q=0;q<4;++q)
        acc[j][q] = ffma2(r[j], make_float2(w[q], w[q]), acc[j][q]);
    }
#pragma unroll
    for (int q=0;q<4;++q) w[q] = wn[q];
  }
}

__device__ __forceinline__ void acc_zero(float2 acc[8][4]){
#pragma unroll
  for (int q=0;q<4;++q)
#pragma unroll
    for (int j=0;j<8;++j) acc[j][q] = make_float2(0.f, 0.f);
}

__device__ __forceinline__ void acc_store130(float* dst, const float2 acc[8][4], int cg, int rg){
#pragma unroll
  for (int q=0;q<4;++q){
    int col = cg + 32*q;
#pragma unroll
    for (int j=0;j<8;++j)
      *reinterpret_cast<float2*>(&dst[col*130 + 16*rg + 2*j]) = acc[j][q];
  }
}

__device__ __forceinline__ void acc_gstore(float* __restrict__ G, const float2 acc[8][4],
                                           int cg, int rg, size_t row0){
#pragma unroll
  for (int j=0;j<8;++j){
    int r0 = 16*rg + 2*j;
#pragma unroll
    for (int q=0;q<4;++q){
      int col = cg + 32*q;
      G[(row0 + r0    )*DM + col] = acc[j][q].x;
      G[(row0 + r0 + 1)*DM + col] = acc[j][q].y;
    }
  }
}

// =================== pair GEMM (64 thr, 16 rows) ============================
// input col-major stride `stride` (even), 16 rows. Thread (cg=lane, rh=half)
// owns cols 4cg..4cg+3 (float4 weight loads) and rows 8rh..8rh+7 (4 pairs).
template<int NCOLS>
__device__ __forceinline__ void gemm_pair(const float* __restrict__ S, int stride,
                                          const float* __restrict__ W,
                                          const float* __restrict__ bias,
                                          int cg, int rh, float2 acc[4][4])
{
  const float4* W4 = reinterpret_cast<const float4*>(W);
  float4 bb = reinterpret_cast<const float4*>(bias)[cg];
  float ba[4] = { bb.x, bb.y, bb.z, bb.w };
#pragma unroll
  for (int i=0;i<4;++i)
#pragma unroll
    for (int j=0;j<4;++j) acc[j][i] = make_float2(ba[i], ba[i]);

  const float* src = S + 8*rh;
  float4 w = W4[cg];
#pragma unroll 2
  for (int c=0;c<NCOLS;++c){
    float4 wn = w;
    if (c+1 < NCOLS) wn = W4[(c+1)*32 + cg];
    float2 r[4];
#pragma unroll
    for (int j=0;j<4;++j)
      r[j] = *reinterpret_cast<const float2*>(src + c*stride + 2*j);
    float wa[4] = { w.x, w.y, w.z, w.w };
#pragma unroll
    for (int j=0;j<4;++j)
#pragma unroll
      for (int i=0;i<4;++i)
        acc[j][i] = ffma2(r[j], make_float2(wa[i], wa[i]), acc[j][i]);
    w = wn;
  }
}

__device__ __forceinline__ void store_pair(float* dst, const float2 acc[4][4],
                                           int cg, int rh, bool relu){
#pragma unroll
  for (int i=0;i<4;++i){
    int col = 4*cg + i;
#pragma unroll
    for (int j=0;j<4;++j){
      float2 v = acc[j][i];
      if (relu){ v.x = fmaxf(v.x, 0.f); v.y = fmaxf(v.y, 0.f); }
      *reinterpret_cast<float2*>(&dst[col*18 + 8*rh + 2*j]) = v;
    }
  }
}

// ======================= Kernel 1: KNN (top-16, stable) =====================
__device__ __forceinline__ void ins16(float bd[16], int bi[16], float cd, int ci){
#pragma unroll
  for (int j=0;j<16;++j){
    bool p = cd < bd[j];
    float lo = fminf(bd[j], cd);
    float hi = fmaxf(bd[j], cd);
    int ni = p ? ci : bi[j];
    ci = p ? bi[j] : ci;
    bd[j] = lo; cd = hi; bi[j] = ni;
  }
}

__global__ void __launch_bounds__(1024,1) knn_kernel(const float* __restrict__ xyz)
{
  extern __shared__ float4 sp4[];                      // NN float4 = 64 KB
  float* s_d = reinterpret_cast<float*>(sp4 + NN);     // [128][128] = 64 KB
  int*   s_i = reinterpret_cast<int*>(s_d + 128*128);  // [128][128] = 64 KB

  int b  = blockIdx.x >> 5;
  int n0 = (blockIdx.x & 31) << 7;
  const float* xb = xyz + (size_t)b*NN*3;
  for (int i = threadIdx.x; i < NN; i += 1024){
    float x = xb[i*3+0], y = xb[i*3+1], z = xb[i*3+2];
    sp4[i] = make_float4(x, y, z, x*x + y*y + z*z);
  }
  __syncthreads();

  int p = threadIdx.x & 127, h = threadIdx.x >> 7;
  float4 me = sp4[n0 + p];
  float bd[16]; int bi[16];
#pragma unroll
  for (int j=0;j<16;++j){ bd[j] = FINF; bi[j] = 0x7fffffff; }

  int m0 = h << 9;
#pragma unroll 1
  for (int m = m0; m < m0 + 512; m += 2){
    float4 o0 = sp4[m], o1 = sp4[m+1];
    float d0 = me.w + o0.w - 2.f*(me.x*o0.x + me.y*o0.y + me.z*o0.z);
    float d1 = me.w + o1.w - 2.f*(me.x*o1.x + me.y*o1.y + me.z*o1.z);
    float th = bd[15];
    if (d0 < th || d1 < th){
      ins16(bd, bi, d0 < th ? d0 : FINF, m);
      ins16(bd, bi, d1 < bd[15] ? d1 : FINF, m+1);
    }
  }
#pragma unroll
  for (int j=0;j<16;++j){
    s_d[(h*16 + j)*128 + p] = bd[j];
    s_i[(h*16 + j)*128 + p] = bi[j];
  }
  __syncthreads();

  if (threadIdx.x < 128){
    int pp = threadIdx.x;
    float fd[16]; int fi[16];
#pragma unroll
    for (int j=0;j<16;++j){ fd[j] = FINF; fi[j] = 0x7fffffff; }
#pragma unroll 1
    for (int e = 0; e < 128; ++e){
      float d = s_d[e*128 + pp];
      int   i = s_i[e*128 + pp];
      if (d < fd[15] || (d == fd[15] && i < fi[15])){
        float cd = d; int ci = i;
#pragma unroll
        for (int j=0;j<16;++j){
          bool pr = (cd < fd[j]) || (cd == fd[j] && ci < fi[j]);
          float td = fd[j]; int ti = fi[j];
          fd[j] = pr ? cd : td;  fi[j] = pr ? ci : ti;
          cd    = pr ? td : cd;  ci    = pr ? ti : ci;
        }
      }
    }
    int* dst = g_knn + ((size_t)b*NN + n0 + pp)*KK;
#pragma unroll
    for (int j=0;j<16;++j) dst[j] = fi[j];
  }
}

// ======================= Kernel 2: x,q,k,v + qs,ks + norms ==================
#define QKV_SMEM_FLOATS (64*130 + 128*130 + 128*130)

__global__ void __launch_bounds__(256,1) qkv_kernel(
    const float* __restrict__ features,
    const float* __restrict__ fc1_w, const float* __restrict__ fc1_b,
    const float* __restrict__ wq_w,  const float* __restrict__ wk_w,
    const float* __restrict__ wv_w,  const float* __restrict__ sim_w)
{
  extern __shared__ float smq[];
  float* s_feat = smq;                   // 64 cols, stride 130
  float* s_x    = smq + 64*130;          // 128 cols, stride 130
  float* s_t    = smq + 64*130 + 128*130;// 128 cols, stride 130 (q then k)

  int cg = threadIdx.x & 31, rg = threadIdx.x >> 5;
  size_t row0 = (size_t)blockIdx.x * 128;
  const float* simw1 = sim_w + DM;       // rows 1..128 of sim_w

  for (int i = threadIdx.x; i < 128*DP; i += 256){
    int r = i >> 6, c = i & 63;
    s_feat[c*130 + r] = features[(row0 + r)*DP + c];
  }
  __syncthreads();

  { // x = feat @ fc1 + b -> s_x
    float2 acc[8][4];
#pragma unroll
    for (int q=0;q<4;++q){
      float bb = fc1_b[cg + 32*q];
#pragma unroll
      for (int j=0;j<8;++j) acc[j][q] = make_float2(bb, bb);
    }
    gemm4<DP>(s_feat, 130, fc1_w, cg, rg, acc);
    acc_store130(s_x, acc, cg, rg);
  }
  __syncthreads();

  { // q -> g_q and s_t
    float2 acc[8][4]; acc_zero(acc);
    gemm4<DM>(s_x, 130, wq_w, cg, rg, acc);
    acc_gstore(g_q, acc, cg, rg, row0);
    acc_store130(s_t, acc, cg, rg);
  }
  __syncthreads();

  if (threadIdx.x < 128){ // qn
    int r = threadIdx.x;
    float s = 0.f;
    for (int c=0;c<DM;++c){ float v = s_t[c*130 + r]; s += v*v; }
    g_qn[row0 + r] = fmaxf(sqrtf(s), EPSN);
  }
  { // qs = q @ simw1
    float2 acc[8][4]; acc_zero(acc);
    gemm4<DM>(s_t, 130, simw1, cg, rg, acc);
    acc_gstore(g_qs, acc, cg, rg, row0);
  }
  __syncthreads();

  { // k -> g_k and s_t
    float2 acc[8][4]; acc_zero(acc);
    gemm4<DM>(s_x, 130, wk_w, cg, rg, acc);
    acc_gstore(g_k, acc, cg, rg, row0);
    acc_store130(s_t, acc, cg, rg);
  }
  __syncthreads();

  if (threadIdx.x < 128){ // kn
    int r = threadIdx.x;
    float s = 0.f;
    for (int c=0;c<DM;++c){ float v = s_t[c*130 + r]; s += v*v; }
    g_kn[row0 + r] = fmaxf(sqrtf(s), EPSN);
  }
  { // ks = k @ simw1
    float2 acc[8][4]; acc_zero(acc);
    gemm4<DM>(s_t, 130, simw1, cg, rg, acc);
    acc_gstore(g_ks, acc, cg, rg, row0);
  }
  { // v
    float2 acc[8][4]; acc_zero(acc);
    gemm4<DM>(s_x, 130, wv_w, cg, rg, acc);
    acc_gstore(g_v, acc, cg, rg, row0);
  }
}

// ======================= Kernel 3: fused attention block ====================
// Tile = 4 points; each warp-PAIR (64 threads) owns one point end-to-end,
// synchronized only by named barrier (1+pair). No block-wide barriers.
#define PPF 7008                 // floats per point region (16B-aligned)
#define P_PE   0                 // 128 x 18
#define P_A    2304              // 128 x 18
#define P_B    4608              // 128 x 18 (h; later res[128])
#define P_SIM  6912              // 16
#define P_RELP (P_SIM + 16)      // 3 x 16
#define P_IDX  (P_SIM + 64)      // 16 ints
#define P_QN   (P_SIM + 80)
#define MAIN_SMEM_FLOATS (4*PPF)

#define BARP() asm volatile("bar.sync %0, 64;" :: "r"(1+pair) : "memory")

__global__ void __launch_bounds__(256,2) main_kernel(
    const float* __restrict__ xyz,   const float* __restrict__ features,
    const float* __restrict__ fc2_w, const float* __restrict__ fc2_b,
    const float* __restrict__ d1_w,  const float* __restrict__ d1_b,
    const float* __restrict__ d2_w,  const float* __restrict__ d2_b,
    const float* __restrict__ g1_w,  const float* __restrict__ g1_b,
    const float* __restrict__ g2_w,  const float* __restrict__ g2_b,
    const float* __restrict__ sim_w, const float* __restrict__ sim_b,
    float* __restrict__ out_res, float* __restrict__ out_attn)
{
  extern __shared__ float sm[];
  int tid  = threadIdx.x;
  int pair = tid >> 6;
  int t64  = tid & 63;
  int rh   = t64 >> 5;
  int lane = tid & 31;
  int cg   = lane;

  int tile = blockIdx.x;
  int b    = tile >> 10;
  int n0   = (tile & 1023) << 2;
  size_t bN  = (size_t)b*NN;
  size_t gp  = bN + n0 + pair;      // this pair's point

  float* sp    = sm + pair*PPF;
  float* PE    = sp + P_PE;
  float* A     = sp + P_A;
  float* Bf    = sp + P_B;
  float* s_sim = sp + P_SIM;
  float* s_rel = sp + P_RELP;
  int*   s_idx = reinterpret_cast<int*>(sp + P_IDX);
  float* RES   = Bf;                // alias: h dead after Ph6a

  // ---- Ph0: idx, rel_pos, qn ----
  if (t64 < 16){
    int r = t64;
    int nb = g_knn[gp*KK + r];
    s_idx[r] = nb;
    const float* xn = xyz + gp*3;
    const float* xm = xyz + (bN + nb)*3;
    s_rel[0*16 + r] = xn[0] - xm[0];
    s_rel[1*16 + r] = xn[1] - xm[1];
    s_rel[2*16 + r] = xn[2] - xm[2];
  }
  if (t64 == 16) sp[P_QN] = g_qn[gp];
  BARP();

  // ---- Ph1: P1 = relu(rel @ d1 + b) -> A ----
  { float2 acc[4][4]; gemm_pair<3>(s_rel, 16, d1_w, d1_b, cg, rh, acc);
    store_pair(A, acc, cg, rh, true); }
  BARP();

  // ---- Ph2: pe = A @ d2 + b -> PE ----
  { float2 acc[4][4]; gemm_pair<DM>(A, 18, d2_w, d2_b, cg, rh, acc);
    store_pair(PE, acc, cg, rh, false); }
  BARP();

  // ---- Ph3: sim[r] = q.k / (qn*kn) ----
  {
    const float* qp = g_q + gp*DM;
    float qreg[4];
#pragma unroll
    for (int u=0;u<4;++u) qreg[u] = qp[lane + 32*u];
    float qn = sp[P_QN];
#pragma unroll 1
    for (int rr=0; rr<8; ++rr){
      int r  = 8*rh + rr;
      int nb = s_idx[r];
      const float* kp = g_k + (bN + nb)*DM;
      float dt = 0.f;
#pragma unroll
      for (int u=0;u<4;++u) dt += qreg[u]*kp[lane + 32*u];
#pragma unroll
      for (int o=16;o;o>>=1) dt += __shfl_xor_sync(0xffffffffu, dt, o);
      if (lane == 0){
        float kn = g_kn[bN + nb];
        s_sim[r] = dt / (qn * kn);
      }
    }
  }
  BARP();

  // ---- Ph4: t = sim*w0 + qs - ks + sim_b + pe -> A ----
  {
#pragma unroll
    for (int cc=0; cc<2; ++cc){
      int col = t64 + 64*cc;
      float w0  = sim_w[col];
      float base = g_qs[gp*DM + col] + sim_b[col];
#pragma unroll
      for (int r=0; r<16; ++r){
        int nb = s_idx[r];
        float ks = g_ks[(bN + nb)*DM + col];
        A[col*18 + r] = fmaf(s_sim[r], w0, base - ks) + PE[col*18 + r];
      }
    }
  }
  BARP();

  // ---- Ph5: h = relu(A @ g1 + b) -> B ----
  { float2 acc[4][4]; gemm_pair<DM>(A, 18, g1_w, g1_b, cg, rh, acc);
    store_pair(Bf, acc, cg, rh, true); }
  BARP();

  // ---- Ph6a: logits = B @ g2 + b -> A ----
  { float2 acc[4][4]; gemm_pair<DM>(Bf, 18, g2_w, g2_b, cg, rh, acc);
    store_pair(A, acc, cg, rh, false); }
  BARP();

  // ---- Ph6b: softmax over k per col; attn out; res ----
  {
    const float inv_s = 0.08838834764831845f;  // 1/sqrt(128)
#pragma unroll
    for (int cc=0; cc<2; ++cc){
      int col = t64 + 64*cc;
      float l[16];
#pragma unroll
      for (int k=0;k<16;++k) l[k] = A[col*18 + k] * inv_s;
      float m = l[0];
#pragma unroll
      for (int k=1;k<16;++k) m = fmaxf(m, l[k]);
      float s = 0.f;
#pragma unroll
      for (int k=0;k<16;++k){ l[k] = expf(l[k] - m); s += l[k]; }
      float rs = 1.f / s;

      float* ao = out_attn + (gp*KK)*DM + col;
      float racc = 0.f;
#pragma unroll
      for (int k=0;k<16;++k){
        float a = l[k] * rs;
        ao[k*DM] = a;
        float vv = g_v[(bN + s_idx[k])*DM + col];
        racc += a * (vv + PE[col*18 + k]);
      }
      RES[col] = racc;   // overwrites Bf (h) — dead after Ph6a
    }
  }
  BARP();

  // ---- Ph7: out = res @ fc2 + b + features ----
  {
    int o = t64;
    float a0 = fc2_b[o];
#pragma unroll 4
    for (int c=0;c<DM;++c)
      a0 = fmaf(RES[c], fc2_w[c*DP + o], a0);
    out_res[gp*DP + o] = a0 + features[gp*DP + o];
  }
}

// ============================ launcher ======================================
extern "C" void kernel_launch(void* const* d_in, const int* in_sizes, int n_in,
                              void* d_out, int out_size)
{
  (void)in_sizes; (void)n_in; (void)out_size;
  const float* xyz      = (const float*)d_in[0];
  const float* features = (const float*)d_in[1];
  const float* fc1_w    = (const float*)d_in[2];
  const float* fc1_b    = (const float*)d_in[3];
  const float* fc2_w    = (const float*)d_in[4];
  const float* fc2_b    = (const float*)d_in[5];
  const float* d1_w     = (const float*)d_in[6];
  const float* d1_b     = (const float*)d_in[7];
  const float* d2_w     = (const float*)d_in[8];
  const float* d2_b     = (const float*)d_in[9];
  const float* g1_w     = (const float*)d_in[10];
  const float* g1_b     = (const float*)d_in[11];
  const float* g2_w     = (const float*)d_in[12];
  const float* g2_b     = (const float*)d_in[13];
  const float* wq_w     = (const float*)d_in[14];
  const float* wk_w     = (const float*)d_in[15];
  const float* wv_w     = (const float*)d_in[16];
  const float* sim_w    = (const float*)d_in[17];
  const float* sim_b    = (const float*)d_in[18];

  float* out      = (float*)d_out;
  float* out_res  = out;                        // (B,N,DP)
  float* out_attn = out + (size_t)BB*NN*DP;     // (B,N,K,DM)

  const int knn_smem  = NN*sizeof(float4) + 2*128*128*4;     // 192 KB
  const int qkv_smem  = QKV_SMEM_FLOATS * sizeof(float);     // ~162.5 KB
  const int main_smem = MAIN_SMEM_FLOATS * sizeof(float);    // ~109.5 KB

  cudaFuncSetAttribute(knn_kernel,  cudaFuncAttributeMaxDynamicSharedMemorySize, knn_smem);
  cudaFuncSetAttribute(qkv_kernel,  cudaFuncAttributeMaxDynamicSharedMemorySize, qkv_smem);
  cudaFuncSetAttribute(main_kernel, cudaFuncAttributeMaxDynamicSharedMemorySize, main_smem);

  knn_kernel<<<BB*(NN/128), 1024, knn_smem>>>(xyz);
  qkv_kernel<<<(BB*NN)/128, 256, qkv_smem>>>(features, fc1_w, fc1_b,
                                             wq_w, wk_w, wv_w, sim_w);
  main_kernel<<<(BB*NN)/4, 256, main_smem>>>(
      xyz, features, fc2_w, fc2_b, d1_w, d1_b, d2_w, d2_b,
      g1_w, g1_b, g2_w, g2_b, sim_w, sim_b, out_res, out_attn);
}

// round 15
// speedup vs baseline: 1.7757x; 1.7757x over previous
#include <cuda_runtime.h>
#include <cstdint>

#define BB 4
#define NN 4096
#define KK 16
#define DP 64
#define DM 128
#define EPSN 1e-8f
#define FINF 3.402823466e38f

// ---------------- scratch (device globals; no allocation allowed) ----------
__device__ float g_q [BB*NN*DM];    // 8 MB   x @ wq
__device__ float g_k [BB*NN*DM];    // 8 MB   x @ wk
__device__ float g_v [BB*NN*DM];    // 8 MB   x @ wv
__device__ float g_qs[BB*NN*DM];    // 8 MB   q @ sim_w[1:]
__device__ float g_ks[BB*NN*DM];    // 8 MB   k @ sim_w[1:]
__device__ float g_qn[BB*NN];       // ||q|| clamped
__device__ float g_kn[BB*NN];       // ||k|| clamped
__device__ int   g_knn[BB*NN*KK];   // 1 MB

// ---------------- packed fp32x2 FMA (Blackwell FFMA2) ----------------------
__device__ __forceinline__ float2 ffma2(float2 a, float2 b, float2 c){
  float2 d;
  asm("fma.rn.f32x2 %0, %1, %2, %3;"
      : "=l"(reinterpret_cast<unsigned long long&>(d))
      : "l"(reinterpret_cast<unsigned long long&>(a)),
        "l"(reinterpret_cast<unsigned long long&>(b)),
        "l"(reinterpret_cast<unsigned long long&>(c)));
  return d;
}

// =================== qkv-style GEMM (256 thr, 128 rows) =====================
template<int NCOLS>
__device__ __forceinline__ void gemm4(const float* __restrict__ S, int stride,
                                      const float* __restrict__ W,
                                      int cg, int rg, float2 acc[8][4])
{
  const float* src = S + 16*rg;
  float w[4];
#pragma unroll
  for (int q=0;q<4;++q) w[q] = W[cg + 32*q];
#pragma unroll 2
  for (int c=0;c<NCOLS;++c){
    float wn[4];
    if (c+1 < NCOLS){
#pragma unroll
      for (int q=0;q<4;++q) wn[q] = W[(c+1)*DM + cg + 32*q];
    }
    float2 r[8];
#pragma unroll
    for (int j=0;j<8;++j)
      r[j] = *reinterpret_cast<const float2*>(src + c*stride + 2*j);
#pragma unroll
    for (int j=0;j<8;++j){
#pragma unroll
      for (int q=0;q<4;++q)
        acc[j][q] = ffma2(r[j], make_float2(w[q], w[q]), acc[j][q]);
    }
#pragma unroll
    for (int q=0;q<4;++q) w[q] = wn[q];
  }
}

__device__ __forceinline__ void acc_zero(float2 acc[8][4]){
#pragma unroll
  for (int q=0;q<4;++q)
#pragma unroll
    for (int j=0;j<8;++j) acc[j][q] = make_float2(0.f, 0.f);
}

__device__ __forceinline__ void acc_store130(float* dst, const float2 acc[8][4], int cg, int rg){
#pragma unroll
  for (int q=0;q<4;++q){
    int col = cg + 32*q;
#pragma unroll
    for (int j=0;j<8;++j)
      *reinterpret_cast<float2*>(&dst[col*130 + 16*rg + 2*j]) = acc[j][q];
  }
}

__device__ __forceinline__ void acc_gstore(float* __restrict__ G, const float2 acc[8][4],
                                           int cg, int rg, size_t row0){
#pragma unroll
  for (int j=0;j<8;++j){
    int r0 = 16*rg + 2*j;
#pragma unroll
    for (int q=0;q<4;++q){
      int col = cg + 32*q;
      G[(row0 + r0    )*DM + col] = acc[j][q].x;
      G[(row0 + r0 + 1)*DM + col] = acc[j][q].y;
    }
  }
}

// =================== pair GEMM (64 thr, 16 rows) ============================
// Small-NCOLS version (d1: NCOLS=3), column-at-a-time.
template<int NCOLS>
__device__ __forceinline__ void gemm_pair(const float* __restrict__ S, int stride,
                                          const float* __restrict__ W,
                                          const float* __restrict__ bias,
                                          int cg, int rh, float2 acc[4][4])
{
  const float4* W4 = reinterpret_cast<const float4*>(W);
  float4 bb = reinterpret_cast<const float4*>(bias)[cg];
  float ba[4] = { bb.x, bb.y, bb.z, bb.w };
#pragma unroll
  for (int i=0;i<4;++i)
#pragma unroll
    for (int j=0;j<4;++j) acc[j][i] = make_float2(ba[i], ba[i]);

  const float* src = S + 8*rh;
#pragma unroll
  for (int c=0;c<NCOLS;++c){
    float4 w = W4[c*32 + cg];
    float2 r[4];
#pragma unroll
    for (int j=0;j<4;++j)
      r[j] = *reinterpret_cast<const float2*>(src + c*stride + 2*j);
    float wa[4] = { w.x, w.y, w.z, w.w };
#pragma unroll
    for (int j=0;j<4;++j)
#pragma unroll
      for (int i=0;i<4;++i)
        acc[j][i] = ffma2(r[j], make_float2(wa[i], wa[i]), acc[j][i]);
  }
}

// 4-column-grouped version (NCOLS % 4 == 0): batch 16 LDS.64 + 4 LDG.128
// (MLP=20) then 64 FFMA2 — one latency window per 84 issued instructions.
template<int NCOLS>
__device__ __forceinline__ void gemm_pair4(const float* __restrict__ S, int stride,
                                           const float* __restrict__ W,
                                           const float* __restrict__ bias,
                                           int cg, int rh, float2 acc[4][4])
{
  static_assert(NCOLS % 4 == 0, "");
  const float4* W4 = reinterpret_cast<const float4*>(W);
  float4 bb = reinterpret_cast<const float4*>(bias)[cg];
  float ba[4] = { bb.x, bb.y, bb.z, bb.w };
#pragma unroll
  for (int i=0;i<4;++i)
#pragma unroll
    for (int j=0;j<4;++j) acc[j][i] = make_float2(ba[i], ba[i]);

  const float* src = S + 8*rh;
#pragma unroll 1
  for (int c0=0; c0<NCOLS; c0+=4){
    float2 r[4][4];
    float4 w[4];
#pragma unroll
    for (int c=0;c<4;++c){
      w[c] = W4[(c0+c)*32 + cg];
#pragma unroll
      for (int j=0;j<4;++j)
        r[c][j] = *reinterpret_cast<const float2*>(src + (c0+c)*stride + 2*j);
    }
#pragma unroll
    for (int c=0;c<4;++c){
      float wa[4] = { w[c].x, w[c].y, w[c].z, w[c].w };
#pragma unroll
      for (int j=0;j<4;++j)
#pragma unroll
        for (int i=0;i<4;++i)
          acc[j][i] = ffma2(r[c][j], make_float2(wa[i], wa[i]), acc[j][i]);
    }
  }
}

__device__ __forceinline__ void store_pair(float* dst, const float2 acc[4][4],
                                           int cg, int rh, bool relu){
#pragma unroll
  for (int i=0;i<4;++i){
    int col = 4*cg + i;
#pragma unroll
    for (int j=0;j<4;++j){
      float2 v = acc[j][i];
      if (relu){ v.x = fmaxf(v.x, 0.f); v.y = fmaxf(v.y, 0.f); }
      *reinterpret_cast<float2*>(&dst[col*18 + 8*rh + 2*j]) = v;
    }
  }
}

// ======================= Kernel 1: KNN (top-16, stable) =====================
// Proven R4 version (322 us): 128 blocks x 512 threads, 4 threads/point each
// scanning a contiguous 1024-chunk with branchy sorted insertion (strict <
// keeps argsort stability), then (d,idx)-lexicographic merge of 4 lists.
__global__ void __launch_bounds__(512,1) knn_kernel(const float* __restrict__ xyz)
{
  extern __shared__ float4 sp4[];                   // NN float4 = 64 KB
  float* s_d = reinterpret_cast<float*>(sp4 + NN);  // [64][128] = 32 KB
  int*   s_i = reinterpret_cast<int*>(s_d + 64*128);// [64][128] = 32 KB

  int b  = blockIdx.x >> 5;
  int n0 = (blockIdx.x & 31) << 7;
  const float* xb = xyz + (size_t)b*NN*3;
  for (int i = threadIdx.x; i < NN; i += 512){
    float x = xb[i*3+0], y = xb[i*3+1], z = xb[i*3+2];
    sp4[i] = make_float4(x, y, z, x*x + y*y + z*z);
  }
  __syncthreads();

  int p = threadIdx.x & 127, h = threadIdx.x >> 7;
  float4 me = sp4[n0 + p];
  float bd[16]; int bi[16];
#pragma unroll
  for (int j=0;j<16;++j){ bd[j] = FINF; bi[j] = 0x7fffffff; }

  int m0 = h << 10;
#pragma unroll 1
  for (int m = m0; m < m0 + 1024; m += 2){
    float4 o0 = sp4[m], o1 = sp4[m+1];
    float d0 = me.w + o0.w - 2.f*(me.x*o0.x + me.y*o0.y + me.z*o0.z);
    float d1 = me.w + o1.w - 2.f*(me.x*o1.x + me.y*o1.y + me.z*o1.z);
    if (d0 < bd[15]){
      float cd = d0; int ci = m;
#pragma unroll
      for (int j=0;j<16;++j){
        if (cd < bd[j]){ float td=bd[j]; int ti=bi[j]; bd[j]=cd; bi[j]=ci; cd=td; ci=ti; }
      }
    }
    if (d1 < bd[15]){
      float cd = d1; int ci = m+1;
#pragma unroll
      for (int j=0;j<16;++j){
        if (cd < bd[j]){ float td=bd[j]; int ti=bi[j]; bd[j]=cd; bi[j]=ci; cd=td; ci=ti; }
      }
    }
  }
#pragma unroll
  for (int j=0;j<16;++j){
    s_d[(h*16 + j)*128 + p] = bd[j];
    s_i[(h*16 + j)*128 + p] = bi[j];
  }
  __syncthreads();

  if (threadIdx.x < 128){
    int pp = threadIdx.x;
    float fd[16]; int fi[16];
#pragma unroll
    for (int j=0;j<16;++j){ fd[j] = FINF; fi[j] = 0x7fffffff; }
#pragma unroll 1
    for (int e = 0; e < 64; ++e){
      float d = s_d[e*128 + pp];
      int   i = s_i[e*128 + pp];
      if (d < fd[15] || (d == fd[15] && i < fi[15])){
        float cd = d; int ci = i;
#pragma unroll
        for (int j=0;j<16;++j){
          if (cd < fd[j] || (cd == fd[j] && ci < fi[j])){
            float td=fd[j]; int ti=fi[j]; fd[j]=cd; fi[j]=ci; cd=td; ci=ti;
          }
        }
      }
    }
    int* dst = g_knn + ((size_t)b*NN + n0 + pp)*KK;
#pragma unroll
    for (int j=0;j<16;++j) dst[j] = fi[j];
  }
}

// ======================= Kernel 2: x,q,k,v + qs,ks + norms ==================
#define QKV_SMEM_FLOATS (64*130 + 128*130 + 128*130)

__global__ void __launch_bounds__(256,1) qkv_kernel(
    const float* __restrict__ features,
    const float* __restrict__ fc1_w, const float* __restrict__ fc1_b,
    const float* __restrict__ wq_w,  const float* __restrict__ wk_w,
    const float* __restrict__ wv_w,  const float* __restrict__ sim_w)
{
  extern __shared__ float smq[];
  float* s_feat = smq;                   // 64 cols, stride 130
  float* s_x    = smq + 64*130;          // 128 cols, stride 130
  float* s_t    = smq + 64*130 + 128*130;// 128 cols, stride 130 (q then k)

  int cg = threadIdx.x & 31, rg = threadIdx.x >> 5;
  size_t row0 = (size_t)blockIdx.x * 128;
  const float* simw1 = sim_w + DM;       // rows 1..128 of sim_w

  for (int i = threadIdx.x; i < 128*DP; i += 256){
    int r = i >> 6, c = i & 63;
    s_feat[c*130 + r] = features[(row0 + r)*DP + c];
  }
  __syncthreads();

  { // x = feat @ fc1 + b -> s_x
    float2 acc[8][4];
#pragma unroll
    for (int q=0;q<4;++q){
      float bb = fc1_b[cg + 32*q];
#pragma unroll
      for (int j=0;j<8;++j) acc[j][q] = make_float2(bb, bb);
    }
    gemm4<DP>(s_feat, 130, fc1_w, cg, rg, acc);
    acc_store130(s_x, acc, cg, rg);
  }
  __syncthreads();

  { // q -> g_q and s_t
    float2 acc[8][4]; acc_zero(acc);
    gemm4<DM>(s_x, 130, wq_w, cg, rg, acc);
    acc_gstore(g_q, acc, cg, rg, row0);
    acc_store130(s_t, acc, cg, rg);
  }
  __syncthreads();

  if (threadIdx.x < 128){ // qn
    int r = threadIdx.x;
    float s = 0.f;
    for (int c=0;c<DM;++c){ float v = s_t[c*130 + r]; s += v*v; }
    g_qn[row0 + r] = fmaxf(sqrtf(s), EPSN);
  }
  { // qs = q @ simw1
    float2 acc[8][4]; acc_zero(acc);
    gemm4<DM>(s_t, 130, simw1, cg, rg, acc);
    acc_gstore(g_qs, acc, cg, rg, row0);
  }
  __syncthreads();

  { // k -> g_k and s_t
    float2 acc[8][4]; acc_zero(acc);
    gemm4<DM>(s_x, 130, wk_w, cg, rg, acc);
    acc_gstore(g_k, acc, cg, rg, row0);
    acc_store130(s_t, acc, cg, rg);
  }
  __syncthreads();

  if (threadIdx.x < 128){ // kn
    int r = threadIdx.x;
    float s = 0.f;
    for (int c=0;c<DM;++c){ float v = s_t[c*130 + r]; s += v*v; }
    g_kn[row0 + r] = fmaxf(sqrtf(s), EPSN);
  }
  { // ks = k @ simw1
    float2 acc[8][4]; acc_zero(acc);
    gemm4<DM>(s_t, 130, simw1, cg, rg, acc);
    acc_gstore(g_ks, acc, cg, rg, row0);
  }
  { // v
    float2 acc[8][4]; acc_zero(acc);
    gemm4<DM>(s_x, 130, wv_w, cg, rg, acc);
    acc_gstore(g_v, acc, cg, rg, row0);
  }
}

// ======================= Kernel 3: fused attention block ====================
// Tile = 4 points; each warp-PAIR (64 threads) owns one point end-to-end,
// synchronized only by named barrier (1+pair). No block-wide barriers.
#define PPF 7008                 // floats per point region (16B-aligned)
#define P_PE   0                 // 128 x 18
#define P_A    2304              // 128 x 18
#define P_B    4608              // 128 x 18 (h; later res[128])
#define P_SIM  6912              // 16
#define P_RELP (P_SIM + 16)      // 3 x 16
#define P_IDX  (P_SIM + 64)      // 16 ints
#define P_QN   (P_SIM + 80)
#define MAIN_SMEM_FLOATS (4*PPF)

#define BARP() asm volatile("bar.sync %0, 64;" :: "r"(1+pair) : "memory")

__global__ void __launch_bounds__(256,2) main_kernel(
    const float* __restrict__ xyz,   const float* __restrict__ features,
    const float* __restrict__ fc2_w, const float* __restrict__ fc2_b,
    const float* __restrict__ d1_w,  const float* __restrict__ d1_b,
    const float* __restrict__ d2_w,  const float* __restrict__ d2_b,
    const float* __restrict__ g1_w,  const float* __restrict__ g1_b,
    const float* __restrict__ g2_w,  const float* __restrict__ g2_b,
    const float* __restrict__ sim_w, const float* __restrict__ sim_b,
    float* __restrict__ out_res, float* __restrict__ out_attn)
{
  extern __shared__ float sm[];
  int tid  = threadIdx.x;
  int pair = tid >> 6;
  int t64  = tid & 63;
  int rh   = t64 >> 5;
  int lane = tid & 31;
  int cg   = lane;

  int tile = blockIdx.x;
  int b    = tile >> 10;
  int n0   = (tile & 1023) << 2;
  size_t bN  = (size_t)b*NN;
  size_t gp  = bN + n0 + pair;      // this pair's point

  float* sp    = sm + pair*PPF;
  float* PE    = sp + P_PE;
  float* A     = sp + P_A;
  float* Bf    = sp + P_B;
  float* s_sim = sp + P_SIM;
  float* s_rel = sp + P_RELP;
  int*   s_idx = reinterpret_cast<int*>(sp + P_IDX);
  float* RES   = Bf;                // alias: h dead after Ph6a

  // ---- Ph0: idx, rel_pos, qn ----
  if (t64 < 16){
    int r = t64;
    int nb = g_knn[gp*KK + r];
    s_idx[r] = nb;
    const float* xn = xyz + gp*3;
    const float* xm = xyz + (bN + nb)*3;
    s_rel[0*16 + r] = xn[0] - xm[0];
    s_rel[1*16 + r] = xn[1] - xm[1];
    s_rel[2*16 + r] = xn[2] - xm[2];
  }
  if (t64 == 16) sp[P_QN] = g_qn[gp];
  BARP();

  // ---- Ph1: P1 = relu(rel @ d1 + b) -> A ----
  { float2 acc[4][4]; gemm_pair<3>(s_rel, 16, d1_w, d1_b, cg, rh, acc);
    store_pair(A, acc, cg, rh, true); }
  BARP();

  // ---- Ph2: pe = A @ d2 + b -> PE ----
  { float2 acc[4][4]; gemm_pair4<DM>(A, 18, d2_w, d2_b, cg, rh, acc);
    store_pair(PE, acc, cg, rh, false); }
  BARP();

  // ---- Ph3: sim[r] = q.k / (qn*kn) ----
  {
    const float* qp = g_q + gp*DM;
    float qreg[4];
#pragma unroll
    for (int u=0;u<4;++u) qreg[u] = qp[lane + 32*u];
    float qn = sp[P_QN];
#pragma unroll 1
    for (int rr=0; rr<8; ++rr){
      int r  = 8*rh + rr;
      int nb = s_idx[r];
      const float* kp = g_k + (bN + nb)*DM;
      float dt = 0.f;
#pragma unroll
      for (int u=0;u<4;++u) dt += qreg[u]*kp[lane + 32*u];
#pragma unroll
      for (int o=16;o;o>>=1) dt += __shfl_xor_sync(0xffffffffu, dt, o);
      if (lane == 0){
        float kn = g_kn[bN + nb];
        s_sim[r] = dt / (qn * kn);
      }
    }
  }
  BARP();

  // ---- Ph4: t = sim*w0 + qs - ks + sim_b + pe -> A ----
  {
#pragma unroll
    for (int cc=0; cc<2; ++cc){
      int col = t64 + 64*cc;
      float w0  = sim_w[col];
      float base = g_qs[gp*DM + col] + sim_b[col];
#pragma unroll
      for (int r=0; r<16; ++r){
        int nb = s_idx[r];
        float ks = g_ks[(bN + nb)*DM + col];
        A[col*18 + r] = fmaf(s_sim[r], w0, base - ks) + PE[col*18 + r];
      }
    }
  }
  BARP();

  // ---- Ph5: h = relu(A @ g1 + b) -> B ----
  { float2 acc[4][4]; gemm_pair4<DM>(A, 18, g1_w, g1_b, cg, rh, acc);
    store_pair(Bf, acc, cg, rh, true); }
  BARP();

  // ---- Ph6a: logits = B @ g2 + b -> A ----
  { float2 acc[4][4]; gemm_pair4<DM>(Bf, 18, g2_w, g2_b, cg, rh, acc);
    store_pair(A, acc, cg, rh, false); }
  BARP();

  // ---- Ph6b: softmax over k per col; attn out; res ----
  {
    const float inv_s = 0.08838834764831845f;  // 1/sqrt(128)
#pragma unroll
    for (int cc=0; cc<2; ++cc){
      int col = t64 + 64*cc;
      float l[16];
#pragma unroll
      for (int k=0;k<16;++k) l[k] = A[col*18 + k] * inv_s;
      float m = l[0];
#pragma unroll
      for (int k=1;k<16;++k) m = fmaxf(m, l[k]);
      float s = 0.f;
#pragma unroll
      for (int k=0;k<16;++k){ l[k] = expf(l[k] - m); s += l[k]; }
      float rs = 1.f / s;

      float* ao = out_attn + (gp*KK)*DM + col;
      float racc = 0.f;
#pragma unroll
      for (int k=0;k<16;++k){
        float a = l[k] * rs;
        ao[k*DM] = a;
        float vv = g_v[(bN + s_idx[k])*DM + col];
        racc += a * (vv + PE[col*18 + k]);
      }
      RES[col] = racc;   // overwrites Bf (h) — dead after Ph6a
    }
  }
  BARP();

  // ---- Ph7: out = res @ fc2 + b + features ----
  {
    int o = t64;
    float a0 = fc2_b[o];
#pragma unroll 4
    for (int c=0;c<DM;++c)
      a0 = fmaf(RES[c], fc2_w[c*DP + o], a0);
    out_res[gp*DP + o] = a0 + features[gp*DP + o];
  }
}

// ============================ launcher ======================================
extern "C" void kernel_launch(void* const* d_in, const int* in_sizes, int n_in,
                              void* d_out, int out_size)
{
  (void)in_sizes; (void)n_in; (void)out_size;
  const float* xyz      = (const float*)d_in[0];
  const float* features = (const float*)d_in[1];
  const float* fc1_w    = (const float*)d_in[2];
  const float* fc1_b    = (const float*)d_in[3];
  const float* fc2_w    = (const float*)d_in[4];
  const float* fc2_b    = (const float*)d_in[5];
  const float* d1_w     = (const float*)d_in[6];
  const float* d1_b     = (const float*)d_in[7];
  const float* d2_w     = (const float*)d_in[8];
  const float* d2_b     = (const float*)d_in[9];
  const float* g1_w     = (const float*)d_in[10];
  const float* g1_b     = (const float*)d_in[11];
  const float* g2_w     = (const float*)d_in[12];
  const float* g2_b     = (const float*)d_in[13];
  const float* wq_w     = (const float*)d_in[14];
  const float* wk_w     = (const float*)d_in[15];
  const float* wv_w     = (const float*)d_in[16];
  const float* sim_w    = (const float*)d_in[17];
  const float* sim_b    = (const float*)d_in[18];

  float* out      = (float*)d_out;
  float* out_res  = out;                        // (B,N,DP)
  float* out_attn = out + (size_t)BB*NN*DP;     // (B,N,K,DM)

  const int knn_smem  = NN*sizeof(float4) + 64*128*8;        // 128 KB
  const int qkv_smem  = QKV_SMEM_FLOATS * sizeof(float);     // ~162.5 KB
  const int main_smem = MAIN_SMEM_FLOATS * sizeof(float);    // ~109.5 KB

  cudaFuncSetAttribute(knn_kernel,  cudaFuncAttributeMaxDynamicSharedMemorySize, knn_smem);
  cudaFuncSetAttribute(qkv_kernel,  cudaFuncAttributeMaxDynamicSharedMemorySize, qkv_smem);
  cudaFuncSetAttribute(main_kernel, cudaFuncAttributeMaxDynamicSharedMemorySize, main_smem);

  knn_kernel<<<BB*(NN/128), 512, knn_smem>>>(xyz);
  qkv_kernel<<<(BB*NN)/128, 256, qkv_smem>>>(features, fc1_w, fc1_b,
                                             wq_w, wk_w, wv_w, sim_w);
  main_kernel<<<(BB*NN)/4, 256, main_smem>>>(
      xyz, features, fc2_w, fc2_b, d1_w, d1_b, d2_w, d2_b,
      g1_w, g1_b, g2_w, g2_b, sim_w, sim_b, out_res, out_attn);
}